// round 1
// baseline (speedup 1.0000x reference)
#include <cuda_runtime.h>
#include <cstdint>

// ---------------------------------------------------------------------------
// Problem constants
//   B=4, T=2048, C=1024, H=16, DQK=DV=64
//   q,k,v scratch: [B,H,T,64]  y scratch: [B,T,H*64] = [8192,1024]
// ---------------------------------------------------------------------------
#define BB   4
#define TT   2048
#define CC   1024
#define HH   16
#define DD   64
#define MROWS (BB*TT)          // 8192

__device__ float g_q[BB*HH*TT*DD];
__device__ float g_k[BB*HH*TT*DD];
__device__ float g_v[BB*HH*TT*DD];
__device__ float g_y[MROWS*CC];

// ---------------------------------------------------------------------------
// 128x128x(K=1024) fp32 GEMM, 256 threads, 8x8 per thread, double-buffered.
//   BT    = true : B is [N,K] row-major (A * B^T)   -- projections
//   BT    = false: B is [K,N] row-major (A * B)     -- output projection
//   QKVO  = true : epilogue scatters to [b,h,t,d] layout (per-head)
// A is [M=8192, K=1024] row-major. N = 1024.
// ---------------------------------------------------------------------------
template <bool BT, bool QKVO>
__global__ __launch_bounds__(256)
void gemm128(const float* __restrict__ A, const float* __restrict__ B,
             float* __restrict__ C)
{
    const int tid = threadIdx.x;
    const int tx  = tid & 15;        // 0..15  (n direction)
    const int ty  = tid >> 4;        // 0..15  (m direction)
    const int m0  = blockIdx.x * 128;
    const int n0  = blockIdx.y * 128;

    __shared__ float As[2][8][132];  // [k][m], padded: conflict-free transpose
    __shared__ float Bs[2][8][132];  // BT: [k][n] transposed; NN: [k][n] direct

    float acc[8][8];
#pragma unroll
    for (int i = 0; i < 8; i++)
#pragma unroll
        for (int j = 0; j < 8; j++) acc[i][j] = 0.f;

    // ---- global load addressing -------------------------------------------
    const int ar = tid >> 1;               // 0..127
    const int ac = (tid & 1) * 4;          // 0 or 4
    const float* Aptr = A + (m0 + ar) * 1024 + ac;

    const float* Bptr;
    int br, bc;
    if (BT) { br = tid >> 1;  bc = (tid & 1) * 4;  Bptr = B + (n0 + br) * 1024 + bc; }
    else    { br = tid >> 5;  bc = (tid & 31) * 4; Bptr = B + br * 1024 + n0 + bc; }

    // ---- prologue: tile 0 --------------------------------------------------
    {
        float4 a = *(const float4*)(Aptr);
        float4 b = *(const float4*)(Bptr);
        As[0][ac + 0][ar] = a.x; As[0][ac + 1][ar] = a.y;
        As[0][ac + 2][ar] = a.z; As[0][ac + 3][ar] = a.w;
        if (BT) {
            Bs[0][bc + 0][br] = b.x; Bs[0][bc + 1][br] = b.y;
            Bs[0][bc + 2][br] = b.z; Bs[0][bc + 3][br] = b.w;
        } else {
            *(float4*)&Bs[0][br][bc] = b;
        }
    }
    __syncthreads();

#pragma unroll 1
    for (int kt = 0; kt < 128; kt++) {
        const int cur = kt & 1;
        float4 an, bn;
        if (kt < 127) {
            an = *(const float4*)(Aptr + (kt + 1) * 8);
            bn = BT ? *(const float4*)(Bptr + (kt + 1) * 8)
                    : *(const float4*)(Bptr + (kt + 1) * 8 * 1024);
        }
#pragma unroll
        for (int kk = 0; kk < 8; kk++) {
            float4 a0 = *(float4*)&As[cur][kk][ty * 8];
            float4 a1 = *(float4*)&As[cur][kk][ty * 8 + 4];
            float4 b0 = *(float4*)&Bs[cur][kk][tx * 8];
            float4 b1 = *(float4*)&Bs[cur][kk][tx * 8 + 4];
            float av[8] = {a0.x, a0.y, a0.z, a0.w, a1.x, a1.y, a1.z, a1.w};
            float bv[8] = {b0.x, b0.y, b0.z, b0.w, b1.x, b1.y, b1.z, b1.w};
#pragma unroll
            for (int i = 0; i < 8; i++)
#pragma unroll
                for (int j = 0; j < 8; j++) acc[i][j] += av[i] * bv[j];
        }
        if (kt < 127) {
            const int nb = cur ^ 1;
            As[nb][ac + 0][ar] = an.x; As[nb][ac + 1][ar] = an.y;
            As[nb][ac + 2][ar] = an.z; As[nb][ac + 3][ar] = an.w;
            if (BT) {
                Bs[nb][bc + 0][br] = bn.x; Bs[nb][bc + 1][br] = bn.y;
                Bs[nb][bc + 2][br] = bn.z; Bs[nb][bc + 3][br] = bn.w;
            } else {
                *(float4*)&Bs[nb][br][bc] = bn;
            }
        }
        __syncthreads();
    }

    // ---- epilogue ----------------------------------------------------------
    if (QKVO) {
        const int nn = n0 + tx * 8;          // 8 | 64, so one head per group
        const int h  = nn >> 6;
        const int d0 = nn & 63;
#pragma unroll
        for (int i = 0; i < 8; i++) {
            const int m = m0 + ty * 8 + i;
            const int b = m >> 11;           // /2048
            const int t = m & 2047;
            float* o = C + (((b * HH + h) * TT + t) * DD + d0);
            *(float4*)o       = make_float4(acc[i][0], acc[i][1], acc[i][2], acc[i][3]);
            *(float4*)(o + 4) = make_float4(acc[i][4], acc[i][5], acc[i][6], acc[i][7]);
        }
    } else {
#pragma unroll
        for (int i = 0; i < 8; i++) {
            float* o = C + (m0 + ty * 8 + i) * 1024 + n0 + tx * 8;
            *(float4*)o       = make_float4(acc[i][0], acc[i][1], acc[i][2], acc[i][3]);
            *(float4*)(o + 4) = make_float4(acc[i][4], acc[i][5], acc[i][6], acc[i][7]);
        }
    }
}

// ---------------------------------------------------------------------------
// Causal flash attention, D=64, 64 q-rows per CTA, 256 threads (4x4/thread).
// grid = (T/64, B*H). q,k,v in [bh, t, d] layout; y out in [b, t, h, d].
// ---------------------------------------------------------------------------
__global__ __launch_bounds__(256)
void attn64(const float* __restrict__ Qg, const float* __restrict__ Kg,
            const float* __restrict__ Vg, float* __restrict__ Y)
{
    const int tid = threadIdx.x;
    const int tx  = tid & 15;          // key/value-d cols (4 each)
    const int ty  = tid >> 4;          // query rows (4 each)
    const int qt  = blockIdx.x;
    const int bh  = blockIdx.y;
    const int b   = bh >> 4;
    const int h   = bh & 15;

    const float* q = Qg + (size_t)bh * TT * DD;
    const float* k = Kg + (size_t)bh * TT * DD;
    const float* v = Vg + (size_t)bh * TT * DD;

    __shared__ float QsT[64][64];      // [d][m], scaled by 1/8
    __shared__ float KP[64][64];       // phase 1: K^T [d][n]; phase 2: P [m][n]
    __shared__ float Vs[64][64];       // [n][d]

    const int q0 = qt * 64;

    // ---- load Q transposed + pre-scale ------------------------------------
    {
        const int r  = tid & 63;       // 32 consecutive rows per warp -> conflict-free
        const int cb = tid >> 6;       // 0..3
#pragma unroll
        for (int i = 0; i < 4; i++) {
            const int cI = cb + i * 4;                 // float4 column 0..15
            float4 val = *(const float4*)(q + (q0 + r) * 64 + cI * 4);
            QsT[cI * 4 + 0][r] = val.x * 0.125f;
            QsT[cI * 4 + 1][r] = val.y * 0.125f;
            QsT[cI * 4 + 2][r] = val.z * 0.125f;
            QsT[cI * 4 + 3][r] = val.w * 0.125f;
        }
    }

    float accO[4][4];
    float mrow[4], lrow[4];
#pragma unroll
    for (int i = 0; i < 4; i++) {
        mrow[i] = -1e30f; lrow[i] = 0.f;
#pragma unroll
        for (int j = 0; j < 4; j++) accO[i][j] = 0.f;
    }

    for (int kt = 0; kt <= qt; kt++) {
        const int k0 = kt * 64;
        __syncthreads();               // protect KP/Vs from previous iteration

        // ---- load K transposed, V direct ----------------------------------
        {
            const int r  = tid & 63;
            const int cb = tid >> 6;
#pragma unroll
            for (int i = 0; i < 4; i++) {
                const int cI = cb + i * 4;
                float4 val = *(const float4*)(k + (k0 + r) * 64 + cI * 4);
                KP[cI * 4 + 0][r] = val.x;
                KP[cI * 4 + 1][r] = val.y;
                KP[cI * 4 + 2][r] = val.z;
                KP[cI * 4 + 3][r] = val.w;
            }
#pragma unroll
            for (int i = 0; i < 4; i++) {
                const int idx = tid + i * 256;
                const int rr  = idx >> 4;
                const int cc  = (idx & 15) * 4;
                *(float4*)&Vs[rr][cc] = *(const float4*)(v + (k0 + rr) * 64 + cc);
            }
        }
        __syncthreads();

        // ---- S = (Q/8) K^T -------------------------------------------------
        float s[4][4];
#pragma unroll
        for (int i = 0; i < 4; i++)
#pragma unroll
            for (int j = 0; j < 4; j++) s[i][j] = 0.f;

#pragma unroll 8
        for (int kk = 0; kk < 64; kk++) {
            float4 qv = *(float4*)&QsT[kk][ty * 4];
            float4 kv = *(float4*)&KP[kk][tx * 4];
            float qa[4] = {qv.x, qv.y, qv.z, qv.w};
            float ka[4] = {kv.x, kv.y, kv.z, kv.w};
#pragma unroll
            for (int i = 0; i < 4; i++)
#pragma unroll
                for (int j = 0; j < 4; j++) s[i][j] += qa[i] * ka[j];
        }

        // ---- causal mask (diagonal tile only) -----------------------------
        if (kt == qt) {
#pragma unroll
            for (int i = 0; i < 4; i++)
#pragma unroll
                for (int j = 0; j < 4; j++)
                    if (tx * 4 + j > ty * 4 + i) s[i][j] = -1e30f;
        }

        // ---- online softmax (row group = 16 contiguous lanes) -------------
#pragma unroll
        for (int i = 0; i < 4; i++) {
            float mx = fmaxf(fmaxf(s[i][0], s[i][1]), fmaxf(s[i][2], s[i][3]));
#pragma unroll
            for (int o = 8; o >= 1; o >>= 1)
                mx = fmaxf(mx, __shfl_xor_sync(0xffffffffu, mx, o));
            const float mn    = fmaxf(mrow[i], mx);
            const float scale = __expf(mrow[i] - mn);
            float rs = 0.f;
#pragma unroll
            for (int j = 0; j < 4; j++) {
                s[i][j] = __expf(s[i][j] - mn);
                rs += s[i][j];
            }
#pragma unroll
            for (int o = 8; o >= 1; o >>= 1)
                rs += __shfl_xor_sync(0xffffffffu, rs, o);
            lrow[i] = lrow[i] * scale + rs;
            mrow[i] = mn;
#pragma unroll
            for (int j = 0; j < 4; j++) accO[i][j] *= scale;
        }

        __syncthreads();               // KP (K^T) reads finished
        // ---- store P into KP as [m][n] ------------------------------------
#pragma unroll
        for (int i = 0; i < 4; i++)
#pragma unroll
            for (int j = 0; j < 4; j++)
                KP[ty * 4 + i][tx * 4 + j] = s[i][j];
        __syncthreads();

        // ---- O += P V ------------------------------------------------------
#pragma unroll 8
        for (int nn = 0; nn < 64; nn++) {
            float4 vv = *(float4*)&Vs[nn][tx * 4];
            float va[4] = {vv.x, vv.y, vv.z, vv.w};
            float p0 = KP[ty * 4 + 0][nn];
            float p1 = KP[ty * 4 + 1][nn];
            float p2 = KP[ty * 4 + 2][nn];
            float p3 = KP[ty * 4 + 3][nn];
#pragma unroll
            for (int j = 0; j < 4; j++) {
                accO[0][j] += p0 * va[j];
                accO[1][j] += p1 * va[j];
                accO[2][j] += p2 * va[j];
                accO[3][j] += p3 * va[j];
            }
        }
    }

    // ---- epilogue: y[b, t, h, d] ------------------------------------------
#pragma unroll
    for (int i = 0; i < 4; i++) {
        const float inv = 1.0f / lrow[i];
        const int t = q0 + ty * 4 + i;
        float* o = Y + (((size_t)(b * TT + t) * HH + h) * DD + tx * 4);
        *(float4*)o = make_float4(accO[i][0] * inv, accO[i][1] * inv,
                                  accO[i][2] * inv, accO[i][3] * inv);
    }
}

// ---------------------------------------------------------------------------
// launch
// ---------------------------------------------------------------------------
extern "C" void kernel_launch(void* const* d_in, const int* in_sizes, int n_in,
                              void* d_out, int out_size)
{
    const float* x_q = (const float*)d_in[0];
    const float* w_q = (const float*)d_in[1];
    const float* w_k = (const float*)d_in[2];
    const float* w_v = (const float*)d_in[3];
    const float* w_o = (const float*)d_in[4];
    float* out = (float*)d_out;

    float* gq; cudaGetSymbolAddress((void**)&gq, g_q);
    float* gk; cudaGetSymbolAddress((void**)&gk, g_k);
    float* gv; cudaGetSymbolAddress((void**)&gv, g_v);
    float* gy; cudaGetSymbolAddress((void**)&gy, g_y);

    dim3 gridP(MROWS / 128, CC / 128);   // 64 x 8
    gemm128<true,  true ><<<gridP, 256>>>(x_q, w_q, gq);
    gemm128<true,  true ><<<gridP, 256>>>(x_q, w_k, gk);
    gemm128<true,  true ><<<gridP, 256>>>(x_q, w_v, gv);

    dim3 gridA(TT / 64, BB * HH);        // 32 x 64
    attn64<<<gridA, 256>>>(gq, gk, gv, gy);

    dim3 gridO(MROWS / 128, CC / 128);   // 64 x 8
    gemm128<false, false><<<gridO, 256>>>(gy, w_o, out);
}

// round 2
// speedup vs baseline: 1.0084x; 1.0084x over previous
#include <cuda_runtime.h>
#include <cstdint>

// ---------------------------------------------------------------------------
// Problem constants
//   B=4, T=2048, C=1024, H=16, DQK=DV=64
//   q,k,v scratch: [B,H,T,64]  y scratch: [B,T,H*64] = [8192,1024]
// ---------------------------------------------------------------------------
#define BB   4
#define TT   2048
#define CC   1024
#define HH   16
#define DD   64
#define MROWS (BB*TT)          // 8192

__device__ float g_q[BB*HH*TT*DD];
__device__ float g_k[BB*HH*TT*DD];
__device__ float g_v[BB*HH*TT*DD];
__device__ float g_y[MROWS*CC];

// ---------------------------------------------------------------------------
// 128x128x(K=1024) fp32 GEMM, 256 threads, 8x8 per thread, double-buffered.
//   BT    = true : B is [N,K] row-major (A * B^T)   -- projections
//   BT    = false: B is [K,N] row-major (A * B)     -- output projection
//   QKVO  = true : epilogue scatters to [b,h,t,d] layout (per-head)
// A is [M=8192, K=1024] row-major. N = 1024.
// ---------------------------------------------------------------------------
template <bool BT, bool QKVO>
__global__ __launch_bounds__(256)
void gemm128(const float* __restrict__ A, const float* __restrict__ B,
             float* __restrict__ C)
{
    const int tid = threadIdx.x;
    const int tx  = tid & 15;        // 0..15  (n direction)
    const int ty  = tid >> 4;        // 0..15  (m direction)
    const int m0  = blockIdx.x * 128;
    const int n0  = blockIdx.y * 128;

    __shared__ float As[2][8][132];  // [k][m], padded: conflict-free transpose
    __shared__ float Bs[2][8][132];  // BT: [k][n] transposed; NN: [k][n] direct

    float acc[8][8];
#pragma unroll
    for (int i = 0; i < 8; i++)
#pragma unroll
        for (int j = 0; j < 8; j++) acc[i][j] = 0.f;

    // ---- global load addressing -------------------------------------------
    const int ar = tid >> 1;               // 0..127
    const int ac = (tid & 1) * 4;          // 0 or 4
    const float* Aptr = A + (m0 + ar) * 1024 + ac;

    const float* Bptr;
    int br, bc;
    if (BT) { br = tid >> 1;  bc = (tid & 1) * 4;  Bptr = B + (n0 + br) * 1024 + bc; }
    else    { br = tid >> 5;  bc = (tid & 31) * 4; Bptr = B + br * 1024 + n0 + bc; }

    // ---- prologue: tile 0 --------------------------------------------------
    {
        float4 a = *(const float4*)(Aptr);
        float4 b = *(const float4*)(Bptr);
        As[0][ac + 0][ar] = a.x; As[0][ac + 1][ar] = a.y;
        As[0][ac + 2][ar] = a.z; As[0][ac + 3][ar] = a.w;
        if (BT) {
            Bs[0][bc + 0][br] = b.x; Bs[0][bc + 1][br] = b.y;
            Bs[0][bc + 2][br] = b.z; Bs[0][bc + 3][br] = b.w;
        } else {
            *(float4*)&Bs[0][br][bc] = b;
        }
    }
    __syncthreads();

#pragma unroll 1
    for (int kt = 0; kt < 128; kt++) {
        const int cur = kt & 1;
        float4 an, bn;
        if (kt < 127) {
            an = *(const float4*)(Aptr + (kt + 1) * 8);
            bn = BT ? *(const float4*)(Bptr + (kt + 1) * 8)
                    : *(const float4*)(Bptr + (kt + 1) * 8 * 1024);
        }
#pragma unroll
        for (int kk = 0; kk < 8; kk++) {
            float4 a0 = *(float4*)&As[cur][kk][ty * 8];
            float4 a1 = *(float4*)&As[cur][kk][ty * 8 + 4];
            float4 b0 = *(float4*)&Bs[cur][kk][tx * 8];
            float4 b1 = *(float4*)&Bs[cur][kk][tx * 8 + 4];
            float av[8] = {a0.x, a0.y, a0.z, a0.w, a1.x, a1.y, a1.z, a1.w};
            float bv[8] = {b0.x, b0.y, b0.z, b0.w, b1.x, b1.y, b1.z, b1.w};
#pragma unroll
            for (int i = 0; i < 8; i++)
#pragma unroll
                for (int j = 0; j < 8; j++) acc[i][j] += av[i] * bv[j];
        }
        if (kt < 127) {
            const int nb = cur ^ 1;
            As[nb][ac + 0][ar] = an.x; As[nb][ac + 1][ar] = an.y;
            As[nb][ac + 2][ar] = an.z; As[nb][ac + 3][ar] = an.w;
            if (BT) {
                Bs[nb][bc + 0][br] = bn.x; Bs[nb][bc + 1][br] = bn.y;
                Bs[nb][bc + 2][br] = bn.z; Bs[nb][bc + 3][br] = bn.w;
            } else {
                *(float4*)&Bs[nb][br][bc] = bn;
            }
        }
        __syncthreads();
    }

    // ---- epilogue ----------------------------------------------------------
    if (QKVO) {
        const int nn = n0 + tx * 8;          // 8 | 64, so one head per group
        const int h  = nn >> 6;
        const int d0 = nn & 63;
#pragma unroll
        for (int i = 0; i < 8; i++) {
            const int m = m0 + ty * 8 + i;
            const int b = m >> 11;           // /2048
            const int t = m & 2047;
            float* o = C + (((b * HH + h) * TT + t) * DD + d0);
            *(float4*)o       = make_float4(acc[i][0], acc[i][1], acc[i][2], acc[i][3]);
            *(float4*)(o + 4) = make_float4(acc[i][4], acc[i][5], acc[i][6], acc[i][7]);
        }
    } else {
#pragma unroll
        for (int i = 0; i < 8; i++) {
            float* o = C + (m0 + ty * 8 + i) * 1024 + n0 + tx * 8;
            *(float4*)o       = make_float4(acc[i][0], acc[i][1], acc[i][2], acc[i][3]);
            *(float4*)(o + 4) = make_float4(acc[i][4], acc[i][5], acc[i][6], acc[i][7]);
        }
    }
}

// ---------------------------------------------------------------------------
// Causal flash attention, D=64, 64 q-rows per CTA, 256 threads (4x4/thread).
// grid = (T/64, B*H). q,k,v in [bh, t, d] layout; y out in [b, t, h, d].
// ---------------------------------------------------------------------------
__global__ __launch_bounds__(256)
void attn64(const float* __restrict__ Qg, const float* __restrict__ Kg,
            const float* __restrict__ Vg, float* __restrict__ Y)
{
    const int tid = threadIdx.x;
    const int tx  = tid & 15;          // key/value-d cols (4 each)
    const int ty  = tid >> 4;          // query rows (4 each)
    const int qt  = blockIdx.x;
    const int bh  = blockIdx.y;
    const int b   = bh >> 4;
    const int h   = bh & 15;

    const float* q = Qg + (size_t)bh * TT * DD;
    const float* k = Kg + (size_t)bh * TT * DD;
    const float* v = Vg + (size_t)bh * TT * DD;

    __shared__ float QsT[64][64];      // [d][m], scaled by 1/8
    __shared__ float KP[64][64];       // phase 1: K^T [d][n]; phase 2: P [m][n]
    __shared__ float Vs[64][64];       // [n][d]

    const int q0 = qt * 64;

    // ---- load Q transposed + pre-scale ------------------------------------
    {
        const int r  = tid & 63;       // 32 consecutive rows per warp -> conflict-free
        const int cb = tid >> 6;       // 0..3
#pragma unroll
        for (int i = 0; i < 4; i++) {
            const int cI = cb + i * 4;                 // float4 column 0..15
            float4 val = *(const float4*)(q + (q0 + r) * 64 + cI * 4);
            QsT[cI * 4 + 0][r] = val.x * 0.125f;
            QsT[cI * 4 + 1][r] = val.y * 0.125f;
            QsT[cI * 4 + 2][r] = val.z * 0.125f;
            QsT[cI * 4 + 3][r] = val.w * 0.125f;
        }
    }

    float accO[4][4];
    float mrow[4], lrow[4];
#pragma unroll
    for (int i = 0; i < 4; i++) {
        mrow[i] = -1e30f; lrow[i] = 0.f;
#pragma unroll
        for (int j = 0; j < 4; j++) accO[i][j] = 0.f;
    }

    for (int kt = 0; kt <= qt; kt++) {
        const int k0 = kt * 64;
        __syncthreads();               // protect KP/Vs from previous iteration

        // ---- load K transposed, V direct ----------------------------------
        {
            const int r  = tid & 63;
            const int cb = tid >> 6;
#pragma unroll
            for (int i = 0; i < 4; i++) {
                const int cI = cb + i * 4;
                float4 val = *(const float4*)(k + (k0 + r) * 64 + cI * 4);
                KP[cI * 4 + 0][r] = val.x;
                KP[cI * 4 + 1][r] = val.y;
                KP[cI * 4 + 2][r] = val.z;
                KP[cI * 4 + 3][r] = val.w;
            }
#pragma unroll
            for (int i = 0; i < 4; i++) {
                const int idx = tid + i * 256;
                const int rr  = idx >> 4;
                const int cc  = (idx & 15) * 4;
                *(float4*)&Vs[rr][cc] = *(const float4*)(v + (k0 + rr) * 64 + cc);
            }
        }
        __syncthreads();

        // ---- S = (Q/8) K^T -------------------------------------------------
        float s[4][4];
#pragma unroll
        for (int i = 0; i < 4; i++)
#pragma unroll
            for (int j = 0; j < 4; j++) s[i][j] = 0.f;

#pragma unroll 8
        for (int kk = 0; kk < 64; kk++) {
            float4 qv = *(float4*)&QsT[kk][ty * 4];
            float4 kv = *(float4*)&KP[kk][tx * 4];
            float qa[4] = {qv.x, qv.y, qv.z, qv.w};
            float ka[4] = {kv.x, kv.y, kv.z, kv.w};
#pragma unroll
            for (int i = 0; i < 4; i++)
#pragma unroll
                for (int j = 0; j < 4; j++) s[i][j] += qa[i] * ka[j];
        }

        // ---- causal mask (diagonal tile only) -----------------------------
        if (kt == qt) {
#pragma unroll
            for (int i = 0; i < 4; i++)
#pragma unroll
                for (int j = 0; j < 4; j++)
                    if (tx * 4 + j > ty * 4 + i) s[i][j] = -1e30f;
        }

        // ---- online softmax (row group = 16 contiguous lanes) -------------
#pragma unroll
        for (int i = 0; i < 4; i++) {
            float mx = fmaxf(fmaxf(s[i][0], s[i][1]), fmaxf(s[i][2], s[i][3]));
#pragma unroll
            for (int o = 8; o >= 1; o >>= 1)
                mx = fmaxf(mx, __shfl_xor_sync(0xffffffffu, mx, o));
            const float mn    = fmaxf(mrow[i], mx);
            const float scale = __expf(mrow[i] - mn);
            float rs = 0.f;
#pragma unroll
            for (int j = 0; j < 4; j++) {
                s[i][j] = __expf(s[i][j] - mn);
                rs += s[i][j];
            }
#pragma unroll
            for (int o = 8; o >= 1; o >>= 1)
                rs += __shfl_xor_sync(0xffffffffu, rs, o);
            lrow[i] = lrow[i] * scale + rs;
            mrow[i] = mn;
#pragma unroll
            for (int j = 0; j < 4; j++) accO[i][j] *= scale;
        }

        __syncthreads();               // KP (K^T) reads finished
        // ---- store P into KP as [m][n] ------------------------------------
#pragma unroll
        for (int i = 0; i < 4; i++)
#pragma unroll
            for (int j = 0; j < 4; j++)
                KP[ty * 4 + i][tx * 4 + j] = s[i][j];
        __syncthreads();

        // ---- O += P V ------------------------------------------------------
#pragma unroll 8
        for (int nn = 0; nn < 64; nn++) {
            float4 vv = *(float4*)&Vs[nn][tx * 4];
            float va[4] = {vv.x, vv.y, vv.z, vv.w};
            float p0 = KP[ty * 4 + 0][nn];
            float p1 = KP[ty * 4 + 1][nn];
            float p2 = KP[ty * 4 + 2][nn];
            float p3 = KP[ty * 4 + 3][nn];
#pragma unroll
            for (int j = 0; j < 4; j++) {
                accO[0][j] += p0 * va[j];
                accO[1][j] += p1 * va[j];
                accO[2][j] += p2 * va[j];
                accO[3][j] += p3 * va[j];
            }
        }
    }

    // ---- epilogue: y[b, t, h, d] ------------------------------------------
#pragma unroll
    for (int i = 0; i < 4; i++) {
        const float inv = 1.0f / lrow[i];
        const int t = q0 + ty * 4 + i;
        float* o = Y + (((size_t)(b * TT + t) * HH + h) * DD + tx * 4);
        *(float4*)o = make_float4(accO[i][0] * inv, accO[i][1] * inv,
                                  accO[i][2] * inv, accO[i][3] * inv);
    }
}

// ---------------------------------------------------------------------------
// launch
// ---------------------------------------------------------------------------
extern "C" void kernel_launch(void* const* d_in, const int* in_sizes, int n_in,
                              void* d_out, int out_size)
{
    const float* x_q = (const float*)d_in[0];
    const float* w_q = (const float*)d_in[1];
    const float* w_k = (const float*)d_in[2];
    const float* w_v = (const float*)d_in[3];
    const float* w_o = (const float*)d_in[4];
    float* out = (float*)d_out;

    float* gq; cudaGetSymbolAddress((void**)&gq, g_q);
    float* gk; cudaGetSymbolAddress((void**)&gk, g_k);
    float* gv; cudaGetSymbolAddress((void**)&gv, g_v);
    float* gy; cudaGetSymbolAddress((void**)&gy, g_y);

    dim3 gridP(MROWS / 128, CC / 128);   // 64 x 8
    gemm128<true,  true ><<<gridP, 256>>>(x_q, w_q, gq);
    gemm128<true,  true ><<<gridP, 256>>>(x_q, w_k, gk);
    gemm128<true,  true ><<<gridP, 256>>>(x_q, w_v, gv);

    dim3 gridA(TT / 64, BB * HH);        // 32 x 64
    attn64<<<gridA, 256>>>(gq, gk, gv, gy);

    dim3 gridO(MROWS / 128, CC / 128);   // 64 x 8
    gemm128<false, false><<<gridO, 256>>>(gy, w_o, out);
}

// round 6
// speedup vs baseline: 1.4293x; 1.4174x over previous
#include <cuda_runtime.h>
#include <cuda_bf16.h>
#include <cstdint>

// ---------------------------------------------------------------------------
// Problem: B=4, T=2048, C=1024, H=16, D=64.  out = attn(xWq, xWk, xWv) Wo
// GEMMs: mma.sync bf16 (family-portable PTX), hi/lo split, fp32 accum.
// Attention: fp32 SIMT flash kernel.
// ---------------------------------------------------------------------------
#define BB   4
#define TT   2048
#define CC   1024
#define HH   16
#define DD   64
#define MROWS (BB*TT)          // 8192
#define KDIM 1024
#define NDIM 1024

// ---- scratch ---------------------------------------------------------------
__device__ float g_q[BB*HH*TT*DD];
__device__ float g_k[BB*HH*TT*DD];
__device__ float g_v[BB*HH*TT*DD];
__device__ __nv_bfloat16 g_xhi[MROWS*KDIM], g_xlo[MROWS*KDIM];
__device__ __nv_bfloat16 g_yhi[MROWS*KDIM], g_ylo[MROWS*KDIM];
__device__ __nv_bfloat16 g_wqhi[NDIM*KDIM], g_wqlo[NDIM*KDIM];
__device__ __nv_bfloat16 g_wkhi[NDIM*KDIM], g_wklo[NDIM*KDIM];
__device__ __nv_bfloat16 g_wvhi[NDIM*KDIM], g_wvlo[NDIM*KDIM];
__device__ __nv_bfloat16 g_wohi[NDIM*KDIM], g_wolo[NDIM*KDIM];

__device__ __forceinline__ uint32_t smem_u32(const void* p) {
    uint32_t a;
    asm("{ .reg .u64 t; cvta.to.shared.u64 t, %1; cvt.u32.u64 %0, t; }"
        : "=r"(a) : "l"(p));
    return a;
}
__device__ __forceinline__ void ldsm4(uint32_t& r0, uint32_t& r1,
                                      uint32_t& r2, uint32_t& r3, uint32_t addr) {
    asm volatile("ldmatrix.sync.aligned.m8n8.x4.shared.b16 {%0,%1,%2,%3}, [%4];"
                 : "=r"(r0), "=r"(r1), "=r"(r2), "=r"(r3) : "r"(addr));
}
#define MMA_BF16(d, a, b0, b1)                                              \
    asm volatile("mma.sync.aligned.m16n8k16.row.col.f32.bf16.bf16.f32 "     \
                 "{%0,%1,%2,%3}, {%4,%5,%6,%7}, {%8,%9}, {%0,%1,%2,%3};"    \
                 : "+f"((d)[0]), "+f"((d)[1]), "+f"((d)[2]), "+f"((d)[3])   \
                 : "r"((a)[0]), "r"((a)[1]), "r"((a)[2]), "r"((a)[3]),      \
                   "r"(b0), "r"(b1))

// ---------------------------------------------------------------------------
// bf16 hi/lo split (elementwise, float4-vectorized)
// ---------------------------------------------------------------------------
__global__ void split_kernel(const float* __restrict__ src,
                             __nv_bfloat16* __restrict__ hi,
                             __nv_bfloat16* __restrict__ lo, int n)
{
    int i = (blockIdx.x * blockDim.x + threadIdx.x) * 4;
    if (i >= n) return;
    float4 v = *(const float4*)(src + i);
    float xs[4] = {v.x, v.y, v.z, v.w};
    __nv_bfloat16 hs[4], ls[4];
#pragma unroll
    for (int j = 0; j < 4; j++) {
        hs[j] = __float2bfloat16_rn(xs[j]);
        ls[j] = __float2bfloat16_rn(xs[j] - __bfloat162float(hs[j]));
    }
    *(__nv_bfloat162*)(hi + i)     = __halves2bfloat162(hs[0], hs[1]);
    *(__nv_bfloat162*)(hi + i + 2) = __halves2bfloat162(hs[2], hs[3]);
    *(__nv_bfloat162*)(lo + i)     = __halves2bfloat162(ls[0], ls[1]);
    *(__nv_bfloat162*)(lo + i + 2) = __halves2bfloat162(ls[2], ls[3]);
}

// transpose-split for w_o: in [K,N] row-major -> out hi/lo [N,K]
__global__ void split_transpose(const float* __restrict__ W,
                                __nv_bfloat16* __restrict__ hi,
                                __nv_bfloat16* __restrict__ lo)
{
    __shared__ float tile[32][33];
    const int n0 = blockIdx.x * 32, k0 = blockIdx.y * 32;
    const int tx = threadIdx.x, ty = threadIdx.y;
    tile[ty][tx] = W[(k0 + ty) * NDIM + n0 + tx];
    __syncthreads();
    float v = tile[tx][ty];
    __nv_bfloat16 h = __float2bfloat16_rn(v);
    __nv_bfloat16 l = __float2bfloat16_rn(v - __bfloat162float(h));
    const int o = (n0 + ty) * KDIM + k0 + tx;
    hi[o] = h;
    lo[o] = l;
}

// ---------------------------------------------------------------------------
// HMMA GEMM: C[128m x 128n] = Ahi.Bhi^T + Ahi.Blo^T + Alo.Bhi^T over K=1024
// A: [M,K] bf16; B: [N,K] bf16. 256 threads = 8 warps (4m x 2n), warp 32x64.
// smem: per stage 4 tiles of 128 rows x 32 halves, padded stride 40 halves.
//   QKV=true : scatter epilogue to [b,h,t,d] fp32
// ---------------------------------------------------------------------------
#define S_ROWB   80                       // bytes per padded row (40 halves)
#define TILE_B   (128 * S_ROWB)           // 10240 bytes per tile
#define STAGE_B  (4 * TILE_B)             // 40960 bytes per stage

template <bool QKV>
__global__ __launch_bounds__(256)
void hmma_gemm(const __nv_bfloat16* __restrict__ Ahi, const __nv_bfloat16* __restrict__ Alo,
               const __nv_bfloat16* __restrict__ Bhi, const __nv_bfloat16* __restrict__ Blo,
               float* __restrict__ C)
{
    extern __shared__ __align__(128) char sm[];   // 2 stages x 40960B
    const int tid  = threadIdx.x;
    const int wid  = tid >> 5;
    const int lane = tid & 31;
    const int m0   = blockIdx.x * 128;
    const int n0   = blockIdx.y * 128;

    const int wm0 = (wid & 3) * 32;      // warp m origin (2 m16 tiles)
    const int wn0 = (wid >> 2) * 64;     // warp n origin (8 n8 tiles)

    // ---- staging addressing: 512 16B-chunks per tile, 2 per thread --------
    const int idx0 = tid, idx1 = tid + 256;
    const int r0c = idx0 >> 2, c0c = idx0 & 3;
    const int r1c = idx1 >> 2, c1c = idx1 & 3;
    const size_t ga0 = (size_t)(m0 + r0c) * KDIM + c0c * 8;
    const size_t ga1 = (size_t)(m0 + r1c) * KDIM + c1c * 8;
    const size_t gb0 = (size_t)(n0 + r0c) * KDIM + c0c * 8;
    const size_t gb1 = (size_t)(n0 + r1c) * KDIM + c1c * 8;
    const uint32_t s0 = r0c * S_ROWB + c0c * 16;
    const uint32_t s1 = r1c * S_ROWB + c1c * 16;

#define LOADG(P, kt)                                                        \
    {                                                                       \
        const int kc = (kt) * 32;                                           \
        P[0] = *(const uint4*)(Ahi + ga0 + kc); P[1] = *(const uint4*)(Ahi + ga1 + kc); \
        P[2] = *(const uint4*)(Alo + ga0 + kc); P[3] = *(const uint4*)(Alo + ga1 + kc); \
        P[4] = *(const uint4*)(Bhi + gb0 + kc); P[5] = *(const uint4*)(Bhi + gb1 + kc); \
        P[6] = *(const uint4*)(Blo + gb0 + kc); P[7] = *(const uint4*)(Blo + gb1 + kc); \
    }
#define STORES(P, st)                                                       \
    {                                                                       \
        char* b = sm + (st) * STAGE_B;                                      \
        *(uint4*)(b + 0 * TILE_B + s0) = P[0]; *(uint4*)(b + 0 * TILE_B + s1) = P[1]; \
        *(uint4*)(b + 1 * TILE_B + s0) = P[2]; *(uint4*)(b + 1 * TILE_B + s1) = P[3]; \
        *(uint4*)(b + 2 * TILE_B + s0) = P[4]; *(uint4*)(b + 2 * TILE_B + s1) = P[5]; \
        *(uint4*)(b + 3 * TILE_B + s0) = P[6]; *(uint4*)(b + 3 * TILE_B + s1) = P[7]; \
    }

    // ---- ldmatrix addresses (byte offsets within a tile) ------------------
    // A (x4): rows m..m+15, chunks ksub*2 + (lane>>4)
    const uint32_t smb = smem_u32(sm);
    const uint32_t aRow = wm0 + (lane & 15);
    const uint32_t aChunkBase = (lane >> 4);         // 0/1
    // B (x4, two n8 tiles): lane groups g=lane>>3
    const uint32_t g = lane >> 3;
    const uint32_t bRow = wn0 + (lane & 7) + ((g >> 1) << 3);  // +8 for g2,g3
    const uint32_t bChunkBase = (g & 1);

    float acc[2][8][4];
#pragma unroll
    for (int i = 0; i < 2; i++)
#pragma unroll
        for (int j = 0; j < 8; j++)
#pragma unroll
            for (int q = 0; q < 4; q++) acc[i][j][q] = 0.f;

    {
        uint4 P[8];
        LOADG(P, 0);
        STORES(P, 0);
    }
    __syncthreads();

    for (int kt = 0; kt < 32; kt++) {
        const int st = kt & 1;
        uint4 P[8];
        if (kt < 31) LOADG(P, kt + 1);

        const uint32_t base = smb + st * STAGE_B;
#pragma unroll
        for (int ksub = 0; ksub < 2; ksub++) {
            uint32_t ahi[2][4], alo[2][4];
#pragma unroll
            for (int mi = 0; mi < 2; mi++) {
                const uint32_t off = (aRow + mi * 16) * S_ROWB
                                   + (ksub * 2 + aChunkBase) * 16;
                ldsm4(ahi[mi][0], ahi[mi][1], ahi[mi][2], ahi[mi][3],
                      base + 0 * TILE_B + off);
                ldsm4(alo[mi][0], alo[mi][1], alo[mi][2], alo[mi][3],
                      base + 1 * TILE_B + off);
            }
            uint32_t bhi[4][4], blo[4][4];
#pragma unroll
            for (int pj = 0; pj < 4; pj++) {
                const uint32_t off = (bRow + pj * 16) * S_ROWB
                                   + (ksub * 2 + bChunkBase) * 16;
                ldsm4(bhi[pj][0], bhi[pj][1], bhi[pj][2], bhi[pj][3],
                      base + 2 * TILE_B + off);
                ldsm4(blo[pj][0], blo[pj][1], blo[pj][2], blo[pj][3],
                      base + 3 * TILE_B + off);
            }
#pragma unroll
            for (int mi = 0; mi < 2; mi++)
#pragma unroll
                for (int nt = 0; nt < 8; nt++) {
                    const int pj = nt >> 1, hh = (nt & 1) * 2;
                    MMA_BF16(acc[mi][nt], ahi[mi], bhi[pj][hh], bhi[pj][hh + 1]);
                    MMA_BF16(acc[mi][nt], ahi[mi], blo[pj][hh], blo[pj][hh + 1]);
                    MMA_BF16(acc[mi][nt], alo[mi], bhi[pj][hh], bhi[pj][hh + 1]);
                }
        }
        __syncthreads();
        if (kt < 31) {
            STORES(P, st ^ 1);
            __syncthreads();
        }
    }

    // ---- epilogue: d-frag thread mapping: rows lane>>2 (+8), cols (lane&3)*2
#pragma unroll
    for (int mi = 0; mi < 2; mi++) {
#pragma unroll
        for (int nt = 0; nt < 8; nt++) {
            const int mrow0 = m0 + wm0 + mi * 16 + (lane >> 2);
            const int ncol  = n0 + wn0 + nt * 8 + (lane & 3) * 2;
            if (QKV) {
                const int h = ncol >> 6, d = ncol & 63;
#pragma unroll
                for (int half = 0; half < 2; half++) {
                    const int m = mrow0 + half * 8;
                    const int b = m >> 11, t = m & 2047;
                    float* o = C + (((size_t)(b * HH + h) * TT + t) * DD + d);
                    *(float2*)o = make_float2(acc[mi][nt][half * 2],
                                              acc[mi][nt][half * 2 + 1]);
                }
            } else {
#pragma unroll
                for (int half = 0; half < 2; half++) {
                    float* o = C + (size_t)(mrow0 + half * 8) * NDIM + ncol;
                    *(float2*)o = make_float2(acc[mi][nt][half * 2],
                                              acc[mi][nt][half * 2 + 1]);
                }
            }
        }
    }
#undef LOADG
#undef STORES
}

// ---------------------------------------------------------------------------
// Causal flash attention, D=64, 64 q-rows per CTA, 256 threads (4x4/thread).
// grid = (T/64, B*H). Outputs y split into bf16 hi/lo [b,t,h,d].
// ---------------------------------------------------------------------------
__global__ __launch_bounds__(256)
void attn64(const float* __restrict__ Qg, const float* __restrict__ Kg,
            const float* __restrict__ Vg,
            __nv_bfloat16* __restrict__ Yhi, __nv_bfloat16* __restrict__ Ylo)
{
    const int tid = threadIdx.x;
    const int tx  = tid & 15;
    const int ty  = tid >> 4;
    const int qt  = blockIdx.x;
    const int bh  = blockIdx.y;
    const int b   = bh >> 4;
    const int h   = bh & 15;

    const float* q = Qg + (size_t)bh * TT * DD;
    const float* k = Kg + (size_t)bh * TT * DD;
    const float* v = Vg + (size_t)bh * TT * DD;

    __shared__ float QsT[64][64];
    __shared__ float KP[64][64];
    __shared__ float Vs[64][64];

    const int q0 = qt * 64;

    {
        const int r  = tid & 63;
        const int cb = tid >> 6;
#pragma unroll
        for (int i = 0; i < 4; i++) {
            const int cI = cb + i * 4;
            float4 val = *(const float4*)(q + (q0 + r) * 64 + cI * 4);
            QsT[cI * 4 + 0][r] = val.x * 0.125f;
            QsT[cI * 4 + 1][r] = val.y * 0.125f;
            QsT[cI * 4 + 2][r] = val.z * 0.125f;
            QsT[cI * 4 + 3][r] = val.w * 0.125f;
        }
    }

    float accO[4][4];
    float mrow[4], lrow[4];
#pragma unroll
    for (int i = 0; i < 4; i++) {
        mrow[i] = -1e30f; lrow[i] = 0.f;
#pragma unroll
        for (int j = 0; j < 4; j++) accO[i][j] = 0.f;
    }

    for (int kt = 0; kt <= qt; kt++) {
        const int k0 = kt * 64;
        __syncthreads();
        {
            const int r  = tid & 63;
            const int cb = tid >> 6;
#pragma unroll
            for (int i = 0; i < 4; i++) {
                const int cI = cb + i * 4;
                float4 val = *(const float4*)(k + (k0 + r) * 64 + cI * 4);
                KP[cI * 4 + 0][r] = val.x;
                KP[cI * 4 + 1][r] = val.y;
                KP[cI * 4 + 2][r] = val.z;
                KP[cI * 4 + 3][r] = val.w;
            }
#pragma unroll
            for (int i = 0; i < 4; i++) {
                const int idx = tid + i * 256;
                const int rr  = idx >> 4;
                const int cc  = (idx & 15) * 4;
                *(float4*)&Vs[rr][cc] = *(const float4*)(v + (k0 + rr) * 64 + cc);
            }
        }
        __syncthreads();

        float s[4][4];
#pragma unroll
        for (int i = 0; i < 4; i++)
#pragma unroll
            for (int j = 0; j < 4; j++) s[i][j] = 0.f;

#pragma unroll 8
        for (int kk = 0; kk < 64; kk++) {
            float4 qv = *(float4*)&QsT[kk][ty * 4];
            float4 kv = *(float4*)&KP[kk][tx * 4];
            float qa[4] = {qv.x, qv.y, qv.z, qv.w};
            float ka[4] = {kv.x, kv.y, kv.z, kv.w};
#pragma unroll
            for (int i = 0; i < 4; i++)
#pragma unroll
                for (int j = 0; j < 4; j++) s[i][j] += qa[i] * ka[j];
        }

        if (kt == qt) {
#pragma unroll
            for (int i = 0; i < 4; i++)
#pragma unroll
                for (int j = 0; j < 4; j++)
                    if (tx * 4 + j > ty * 4 + i) s[i][j] = -1e30f;
        }

#pragma unroll
        for (int i = 0; i < 4; i++) {
            float mx = fmaxf(fmaxf(s[i][0], s[i][1]), fmaxf(s[i][2], s[i][3]));
#pragma unroll
            for (int o = 8; o >= 1; o >>= 1)
                mx = fmaxf(mx, __shfl_xor_sync(0xffffffffu, mx, o));
            const float mn    = fmaxf(mrow[i], mx);
            const float scale = __expf(mrow[i] - mn);
            float rs = 0.f;
#pragma unroll
            for (int j = 0; j < 4; j++) {
                s[i][j] = __expf(s[i][j] - mn);
                rs += s[i][j];
            }
#pragma unroll
            for (int o = 8; o >= 1; o >>= 1)
                rs += __shfl_xor_sync(0xffffffffu, rs, o);
            lrow[i] = lrow[i] * scale + rs;
            mrow[i] = mn;
#pragma unroll
            for (int j = 0; j < 4; j++) accO[i][j] *= scale;
        }

        __syncthreads();
#pragma unroll
        for (int i = 0; i < 4; i++)
#pragma unroll
            for (int j = 0; j < 4; j++)
                KP[ty * 4 + i][tx * 4 + j] = s[i][j];
        __syncthreads();

#pragma unroll 8
        for (int nn = 0; nn < 64; nn++) {
            float4 vv = *(float4*)&Vs[nn][tx * 4];
            float va[4] = {vv.x, vv.y, vv.z, vv.w};
            float p0 = KP[ty * 4 + 0][nn];
            float p1 = KP[ty * 4 + 1][nn];
            float p2 = KP[ty * 4 + 2][nn];
            float p3 = KP[ty * 4 + 3][nn];
#pragma unroll
            for (int j = 0; j < 4; j++) {
                accO[0][j] += p0 * va[j];
                accO[1][j] += p1 * va[j];
                accO[2][j] += p2 * va[j];
                accO[3][j] += p3 * va[j];
            }
        }
    }

    // ---- epilogue: split-write y[b,t,h,d] as bf16 hi/lo -------------------
#pragma unroll
    for (int i = 0; i < 4; i++) {
        const float inv = 1.0f / lrow[i];
        const int t = q0 + ty * 4 + i;
        const size_t off = ((size_t)(b * TT + t)) * CC + h * DD + tx * 4;
        __nv_bfloat16 hs[4], ls[4];
#pragma unroll
        for (int j = 0; j < 4; j++) {
            float val = accO[i][j] * inv;
            hs[j] = __float2bfloat16_rn(val);
            ls[j] = __float2bfloat16_rn(val - __bfloat162float(hs[j]));
        }
        *(__nv_bfloat162*)(Yhi + off)     = __halves2bfloat162(hs[0], hs[1]);
        *(__nv_bfloat162*)(Yhi + off + 2) = __halves2bfloat162(hs[2], hs[3]);
        *(__nv_bfloat162*)(Ylo + off)     = __halves2bfloat162(ls[0], ls[1]);
        *(__nv_bfloat162*)(Ylo + off + 2) = __halves2bfloat162(ls[2], ls[3]);
    }
}

// ---------------------------------------------------------------------------
// launch
// ---------------------------------------------------------------------------
extern "C" void kernel_launch(void* const* d_in, const int* in_sizes, int n_in,
                              void* d_out, int out_size)
{
    const float* x_q = (const float*)d_in[0];
    const float* w_q = (const float*)d_in[1];
    const float* w_k = (const float*)d_in[2];
    const float* w_v = (const float*)d_in[3];
    const float* w_o = (const float*)d_in[4];
    float* out = (float*)d_out;

    float *gq, *gk, *gv;
    cudaGetSymbolAddress((void**)&gq, g_q);
    cudaGetSymbolAddress((void**)&gk, g_k);
    cudaGetSymbolAddress((void**)&gv, g_v);
    __nv_bfloat16 *xhi, *xlo, *yhi, *ylo;
    __nv_bfloat16 *wqhi, *wqlo, *wkhi, *wklo, *wvhi, *wvlo, *wohi, *wolo;
    cudaGetSymbolAddress((void**)&xhi, g_xhi);  cudaGetSymbolAddress((void**)&xlo, g_xlo);
    cudaGetSymbolAddress((void**)&yhi, g_yhi);  cudaGetSymbolAddress((void**)&ylo, g_ylo);
    cudaGetSymbolAddress((void**)&wqhi, g_wqhi); cudaGetSymbolAddress((void**)&wqlo, g_wqlo);
    cudaGetSymbolAddress((void**)&wkhi, g_wkhi); cudaGetSymbolAddress((void**)&wklo, g_wklo);
    cudaGetSymbolAddress((void**)&wvhi, g_wvhi); cudaGetSymbolAddress((void**)&wvlo, g_wvlo);
    cudaGetSymbolAddress((void**)&wohi, g_wohi); cudaGetSymbolAddress((void**)&wolo, g_wolo);

    const int smem = 2 * STAGE_B;   // 81920
    cudaFuncSetAttribute(hmma_gemm<true>,  cudaFuncAttributeMaxDynamicSharedMemorySize, smem);
    cudaFuncSetAttribute(hmma_gemm<false>, cudaFuncAttributeMaxDynamicSharedMemorySize, smem);

    // splits
    split_kernel<<<(MROWS * KDIM / 4 + 255) / 256, 256>>>(x_q, xhi, xlo, MROWS * KDIM);
    split_kernel<<<(NDIM * KDIM / 4 + 255) / 256, 256>>>(w_q, wqhi, wqlo, NDIM * KDIM);
    split_kernel<<<(NDIM * KDIM / 4 + 255) / 256, 256>>>(w_k, wkhi, wklo, NDIM * KDIM);
    split_kernel<<<(NDIM * KDIM / 4 + 255) / 256, 256>>>(w_v, wvhi, wvlo, NDIM * KDIM);
    split_transpose<<<dim3(32, 32), dim3(32, 32)>>>(w_o, wohi, wolo);

    // projections (HMMA)
    dim3 gridG(MROWS / 128, NDIM / 128);     // 64 x 8
    hmma_gemm<true><<<gridG, 256, smem>>>(xhi, xlo, wqhi, wqlo, gq);
    hmma_gemm<true><<<gridG, 256, smem>>>(xhi, xlo, wkhi, wklo, gk);
    hmma_gemm<true><<<gridG, 256, smem>>>(xhi, xlo, wvhi, wvlo, gv);

    // attention (fp32 SIMT), writes split y
    dim3 gridA(TT / 64, BB * HH);            // 32 x 64
    attn64<<<gridA, 256>>>(gq, gk, gv, yhi, ylo);

    // output projection (HMMA)
    hmma_gemm<false><<<gridG, 256, smem>>>(yhi, ylo, wohi, wolo, out);
}